// round 5
// baseline (speedup 1.0000x reference)
#include <cuda_runtime.h>
#include <cstdint>

#define BATCH 8192
#define HID   512
#define HID2  1024
#define NSTEPS 10
#define NEVAL  (NSTEPS*4)

// ---------------- scratch (device globals; no allocation anywhere) -----------
__device__ float g_x1[(size_t)BATCH * HID2];    // tanh out, tf32 + k-permuted
__device__ float g_x2[(size_t)BATCH * HID2];    // tanh out, tf32 + k-permuted
__device__ float g_acc[(size_t)BATCH * HID];    // fp32 RK4 accumulator (natural)
__device__ float g_htmp[(size_t)BATCH * HID];   // tf32 + k-permuted stage input
__device__ float g_h[(size_t)BATCH * HID];      // fp32 state (natural)
__device__ float g_hr[(size_t)BATCH * HID];     // tf32 + k-permuted copy of h
__device__ float g_w1[(size_t)HID2 * HID];      // tf32 + k-permuted weights
__device__ float g_w2[(size_t)HID2 * HID2];
__device__ float g_w3[(size_t)HID  * HID2];
__device__ float g_c1[NEVAL * HID2];            // natural

// ---------------- helpers ----------------------------------------------------
__device__ __forceinline__ float to_tf32(float x) {
    float y;
    asm("cvt.rna.tf32.f32 %0, %1;" : "=f"(y) : "f"(x));
    return y;
}

__device__ __forceinline__ void mma8(float* d, const float* a, const float* b) {
    const unsigned* A = (const unsigned*)a;
    const unsigned* B = (const unsigned*)b;
    asm volatile(
        "mma.sync.aligned.m16n8k8.row.col.f32.tf32.tf32.f32 "
        "{%0,%1,%2,%3}, {%4,%5,%6,%7}, {%8,%9}, {%0,%1,%2,%3};\n"
        : "+f"(d[0]), "+f"(d[1]), "+f"(d[2]), "+f"(d[3])
        : "r"(A[0]), "r"(A[1]), "r"(A[2]), "r"(A[3]), "r"(B[0]), "r"(B[1]));
}

// permutation within each 32-float k-chunk: p(k) = (k&3)*8 + (k>>2)
__device__ __forceinline__ int p32(int k) { return ((k & 3) << 3) + (k >> 2); }

// ---------------- prep kernels -----------------------------------------------
// round to tf32 AND apply the k-chunk permutation (flat array, K % 32 == 0)
__global__ void prep_mat_kernel(const float* __restrict__ src, float* __restrict__ dst, int n) {
    int i = blockIdx.x * blockDim.x + threadIdx.x;
    if (i < n) {
        int base = i & ~31, j = i & 31;
        dst[base + p32(j)] = to_tf32(src[i]);
    }
}

// c1[e][j] = b1[j] + sum_i W1[j,i]*(t_e*Wt[i]+bt[i])   (reads NATURAL W1)
__global__ void c1_all_kernel(const float* __restrict__ W1, const float* __restrict__ b1,
                              const float* __restrict__ Wt, const float* __restrict__ bt,
                              float dt, float* __restrict__ out) {
    int gw = (blockIdx.x * blockDim.x + threadIdx.x) >> 5;
    int lane = threadIdx.x & 31;
    int e = gw >> 10;
    int j = gw & 1023;
    if (e >= NEVAL) return;
    int step = e >> 2, st = e & 3;
    float tv = step * dt + ((st == 0) ? 0.0f : (st == 3) ? dt : 0.5f * dt);
    const float* row = W1 + (size_t)j * HID;
    float s = 0.0f;
    #pragma unroll 4
    for (int i = lane; i < HID; i += 32)
        s = fmaf(row[i], fmaf(tv, Wt[i], bt[i]), s);
    #pragma unroll
    for (int o = 16; o; o >>= 1) s += __shfl_xor_sync(0xffffffffu, s, o);
    if (lane == 0) out[e * HID2 + j] = b1[j] + s;
}

// ---------------- GEMM: C = act( A[M,K] @ Bw[N,K]^T + bias[N] ) --------------
// A/Bw are tf32-rounded AND k-chunk-permuted in global memory.
// cp.async 3-stage pipeline; fragment loads are LDS.128 (conflict-free).
// stage < 0 : tanh epilogue -> C (tf32, permuted). stage 0..3: fused RK4.
__global__ __launch_bounds__(256, 2)
void gemm_kernel(const float* __restrict__ A, const float* __restrict__ Bw,
                 const float* __restrict__ bias, float* __restrict__ C,
                 int N, int K, int stage, float dt,
                 float* __restrict__ hbuf, float* __restrict__ accbuf,
                 float* __restrict__ htmp, float* __restrict__ hr) {
    extern __shared__ float smem[];
    const int LDT = 36;                 // padded stride (floats); 144B rows, 16B-aligned
    const int STG_F = 128 * LDT;
    float* As = smem;                   // 3 stages A, then 3 stages B
    float* Bs = smem + 3 * STG_F;

    const int t = threadIdx.x;
    const int warp = t >> 5, lane = t & 31;
    const int wm = warp & 1, wn = warp >> 1;  // 2 x 4 warp grid, warp tile 64x32
    const int g = lane >> 2, q = lane & 3;
    const int bm = blockIdx.y * 128;
    const int bn = blockIdx.x * 128;

    const int c4  = (t & 7) * 4;
    const int r0l = t >> 3;

    const float* Ag = A  + (size_t)(bm + r0l) * K + c4;
    const float* Bg = Bw + (size_t)(bn + r0l) * K + c4;

    const unsigned stgB = STG_F * 4;
    unsigned sA0 = (unsigned)__cvta_generic_to_shared(As + r0l * LDT + c4);
    unsigned sB0 = (unsigned)__cvta_generic_to_shared(Bs + r0l * LDT + c4);

    float acc[4][4][4];
    #pragma unroll
    for (int i = 0; i < 4; i++)
        #pragma unroll
        for (int j = 0; j < 4; j++)
            #pragma unroll
            for (int v = 0; v < 4; v++) acc[i][j][v] = 0.0f;

    const int KT = K >> 5;

    #define LOAD_CHUNK(kt, s)                                                        \
    {                                                                                \
        const float* ap = Ag + (kt) * 32;                                            \
        const float* bp = Bg + (kt) * 32;                                            \
        unsigned sa = sA0 + (unsigned)(s) * stgB;                                    \
        unsigned sb = sB0 + (unsigned)(s) * stgB;                                    \
        _Pragma("unroll")                                                            \
        for (int i = 0; i < 4; i++) {                                                \
            asm volatile("cp.async.cg.shared.global [%0], [%1], 16;\n"               \
                         :: "r"(sa + i * 32 * LDT * 4), "l"(ap + (size_t)i * 32 * K)); \
            asm volatile("cp.async.cg.shared.global [%0], [%1], 16;\n"               \
                         :: "r"(sb + i * 32 * LDT * 4), "l"(bp + (size_t)i * 32 * K)); \
        }                                                                            \
        asm volatile("cp.async.commit_group;\n");                                    \
    }

    LOAD_CHUNK(0, 0);
    LOAD_CHUNK(1, 1);

    // fragment base offsets (floats): thread's 8 permuted columns start at q*8
    const int aRow0 = wm * 64 + g;      // + fm*16, +8
    const int bRow0 = wn * 32 + g;      // + fn*8

    for (int kt = 0; kt < KT; kt++) {
        asm volatile("cp.async.wait_group 1;\n");
        __syncthreads();
        if (kt + 2 < KT) LOAD_CHUNK(kt + 2, (kt + 2) % 3);

        const int cur = kt % 3;
        const float* Asb = As + cur * STG_F + q * 8;
        const float* Bsb = Bs + cur * STG_F + q * 8;
        #pragma unroll
        for (int sp = 0; sp < 2; sp++) {
            float4 bq[4];
            #pragma unroll
            for (int fn = 0; fn < 4; fn++)
                bq[fn] = *(const float4*)(Bsb + (bRow0 + fn * 8) * LDT + sp * 4);
            #pragma unroll
            for (int fm = 0; fm < 4; fm++) {
                float4 alo = *(const float4*)(Asb + (aRow0 + fm * 16) * LDT + sp * 4);
                float4 ahi = *(const float4*)(Asb + (aRow0 + fm * 16 + 8) * LDT + sp * 4);
                float a0[4] = { alo.x, ahi.x, alo.y, ahi.y };   // s = 2*sp
                float a1[4] = { alo.z, ahi.z, alo.w, ahi.w };   // s = 2*sp+1
                #pragma unroll
                for (int fn = 0; fn < 4; fn++) {
                    float b0[2] = { bq[fn].x, bq[fn].y };
                    float b1[2] = { bq[fn].z, bq[fn].w };
                    mma8(acc[fm][fn], a0, b0);
                    mma8(acc[fm][fn], a1, b1);
                }
            }
        }
        __syncthreads();
    }
    #undef LOAD_CHUNK

    // ---------------- epilogue ----------------
    // thread's natural columns: c = bn + wn*32 + fn*8 + 2q (+1)
    // permuted store offsets within the 32-chunk: o0 = p32(fn*8+2q), o1 = o0+8
    #pragma unroll
    for (int fm = 0; fm < 4; fm++) {
        int r0 = bm + wm * 64 + fm * 16 + g;
        int r1 = r0 + 8;
        #pragma unroll
        for (int fn = 0; fn < 4; fn++) {
            int coff = fn * 8 + 2 * q;                 // 0..30, even
            int c = bn + wn * 32 + coff;               // natural col of v0
            int o0 = p32(coff);
            int cp0 = bn + wn * 32 + o0;               // permuted col of v0
            int cp1 = cp0 + 8;                         // permuted col of v1
            float bc0 = bias[c], bc1 = bias[c + 1];
            float v[4];
            v[0] = acc[fm][fn][0] + bc0;   // (r0, c)
            v[1] = acc[fm][fn][1] + bc1;   // (r0, c+1)
            v[2] = acc[fm][fn][2] + bc0;   // (r1, c)
            v[3] = acc[fm][fn][3] + bc1;   // (r1, c+1)
            if (stage < 0) {
                C[(size_t)r0 * N + cp0] = to_tf32(tanhf(v[0]));
                C[(size_t)r0 * N + cp1] = to_tf32(tanhf(v[1]));
                C[(size_t)r1 * N + cp0] = to_tf32(tanhf(v[2]));
                C[(size_t)r1 * N + cp1] = to_tf32(tanhf(v[3]));
            } else {
                int rows[2] = { r0, r1 };
                #pragma unroll
                for (int u = 0; u < 2; u++) {
                    size_t in0 = (size_t)rows[u] * N + c;       // natural
                    size_t ip0 = (size_t)rows[u] * N + cp0;     // permuted
                    size_t ip1 = (size_t)rows[u] * N + cp1;
                    float k0 = v[u * 2], k1 = v[u * 2 + 1];
                    float h0 = hbuf[in0], h1 = hbuf[in0 + 1];
                    if (stage == 0) {
                        accbuf[in0]     = k0;
                        accbuf[in0 + 1] = k1;
                        htmp[ip0] = to_tf32(h0 + 0.5f * dt * k0);
                        htmp[ip1] = to_tf32(h1 + 0.5f * dt * k1);
                    } else if (stage == 1 || stage == 2) {
                        accbuf[in0]     += 2.0f * k0;
                        accbuf[in0 + 1] += 2.0f * k1;
                        const float co = (stage == 2) ? dt : 0.5f * dt;
                        htmp[ip0] = to_tf32(h0 + co * k0);
                        htmp[ip1] = to_tf32(h1 + co * k1);
                    } else {
                        float hn0 = h0 + (dt / 6.0f) * (accbuf[in0]     + k0);
                        float hn1 = h1 + (dt / 6.0f) * (accbuf[in0 + 1] + k1);
                        hbuf[in0]     = hn0;
                        hbuf[in0 + 1] = hn1;
                        hr[ip0] = to_tf32(hn0);
                        hr[ip1] = to_tf32(hn1);
                    }
                }
            }
        }
    }
}

// ---------------- launch -----------------------------------------------------
extern "C" void kernel_launch(void* const* d_in, const int* in_sizes, int n_in,
                              void* d_out, int out_size) {
    const float* h  = (const float*)d_in[0];
    const float* W1 = (const float*)d_in[1];
    const float* b1 = (const float*)d_in[2];
    const float* W2 = (const float*)d_in[3];
    const float* b2 = (const float*)d_in[4];
    const float* W3 = (const float*)d_in[5];
    const float* b3 = (const float*)d_in[6];
    const float* Wt = (const float*)d_in[7];
    const float* bt = (const float*)d_in[8];
    (void)in_sizes; (void)n_in; (void)out_size;

    float *x1, *x2, *accb, *htmp, *hbuf, *hr, *w1, *w2, *w3, *c1;
    cudaGetSymbolAddress((void**)&x1,   g_x1);
    cudaGetSymbolAddress((void**)&x2,   g_x2);
    cudaGetSymbolAddress((void**)&accb, g_acc);
    cudaGetSymbolAddress((void**)&htmp, g_htmp);
    cudaGetSymbolAddress((void**)&hbuf, g_h);
    cudaGetSymbolAddress((void**)&hr,   g_hr);
    cudaGetSymbolAddress((void**)&w1,   g_w1);
    cudaGetSymbolAddress((void**)&w2,   g_w2);
    cudaGetSymbolAddress((void**)&w3,   g_w3);
    cudaGetSymbolAddress((void**)&c1,   g_c1);

    const int SMEM = 2 * 3 * 128 * 36 * (int)sizeof(float);  // 110592 B
    cudaFuncSetAttribute(gemm_kernel, cudaFuncAttributeMaxDynamicSharedMemorySize, SMEM);

    cudaMemcpyAsync(hbuf, h, (size_t)BATCH * HID * sizeof(float), cudaMemcpyDeviceToDevice);

    const float dt = 1.0f / NSTEPS;

    // prep: tf32-round + permute weights and h, compute all 40 c1 vectors
    {
        int n;
        n = HID2 * HID;   prep_mat_kernel<<<(n + 255) / 256, 256>>>(W1, w1, n);
        n = HID2 * HID2;  prep_mat_kernel<<<(n + 255) / 256, 256>>>(W2, w2, n);
        n = HID * HID2;   prep_mat_kernel<<<(n + 255) / 256, 256>>>(W3, w3, n);
        n = BATCH * HID;  prep_mat_kernel<<<(n + 255) / 256, 256>>>(h, hr, n);
        c1_all_kernel<<<NEVAL * HID2 / 8, 256>>>(W1, b1, Wt, bt, dt, c1);
    }

    dim3 blk(256);
    dim3 grd1(HID2 / 128, BATCH / 128);    // 8 x 64 = 512 CTAs
    dim3 grd3(HID  / 128, BATCH / 128);    // 4 x 64 = 256 CTAs

    for (int s = 0; s < NSTEPS; s++) {
        for (int st = 0; st < 4; st++) {
            const float* Ain = (st == 0) ? hr : htmp;
            const float* c1e = c1 + (s * 4 + st) * HID2;
            gemm_kernel<<<grd1, blk, SMEM>>>(Ain, w1, c1e, x1,
                                             HID2, HID, -1, dt,
                                             nullptr, nullptr, nullptr, nullptr);
            gemm_kernel<<<grd1, blk, SMEM>>>(x1, w2, b2, x2,
                                             HID2, HID2, -1, dt,
                                             nullptr, nullptr, nullptr, nullptr);
            gemm_kernel<<<grd3, blk, SMEM>>>(x2, w3, b3, nullptr,
                                             HID, HID2, st, dt,
                                             hbuf, accb, htmp, hr);
        }
    }

    cudaMemcpyAsync(d_out, hbuf, (size_t)BATCH * HID * sizeof(float), cudaMemcpyDeviceToDevice);
}

// round 6
// speedup vs baseline: 1.2271x; 1.2271x over previous
#include <cuda_runtime.h>
#include <cstdint>

#define BATCH 8192
#define HID   512
#define HID2  1024
#define NSTEPS 10
#define NEVAL  (NSTEPS*4)

// ---------------- scratch (device globals; no allocation anywhere) -----------
__device__ float g_x1[(size_t)BATCH * HID2];    // 32 MB  (tanh out, tf32-rounded)
__device__ float g_x2[(size_t)BATCH * HID2];    // 32 MB
__device__ float g_acc[(size_t)BATCH * HID];    // 16 MB  (fp32 RK4 accumulator)
__device__ float g_htmp[(size_t)BATCH * HID];   // 16 MB  (tf32-rounded stage input)
__device__ float g_h[(size_t)BATCH * HID];      // 16 MB  (fp32 state)
__device__ float g_hr[(size_t)BATCH * HID];     // 16 MB  (tf32-rounded copy of h)
__device__ float g_w1[(size_t)HID2 * HID];      //  2 MB  (tf32-rounded weights)
__device__ float g_w2[(size_t)HID2 * HID2];     //  4 MB
__device__ float g_w3[(size_t)HID  * HID2];     //  2 MB
__device__ float g_c1[NEVAL * HID2];            // 160 KB

// ---------------- helpers ----------------------------------------------------
__device__ __forceinline__ float to_tf32(float x) {
    float y;
    asm("cvt.rna.tf32.f32 %0, %1;" : "=f"(y) : "f"(x));
    return y;
}

__device__ __forceinline__ void mma8(float* d, const float* a, const float* b) {
    const unsigned* A = (const unsigned*)a;
    const unsigned* B = (const unsigned*)b;
    asm volatile(
        "mma.sync.aligned.m16n8k8.row.col.f32.tf32.tf32.f32 "
        "{%0,%1,%2,%3}, {%4,%5,%6,%7}, {%8,%9}, {%0,%1,%2,%3};\n"
        : "+f"(d[0]), "+f"(d[1]), "+f"(d[2]), "+f"(d[3])
        : "r"(A[0]), "r"(A[1]), "r"(A[2]), "r"(A[3]), "r"(B[0]), "r"(B[1]));
}

// ---------------- prep kernels -----------------------------------------------
__global__ void round4_kernel(const float4* __restrict__ src, float4* __restrict__ dst, int n4) {
    int i = blockIdx.x * blockDim.x + threadIdx.x;
    if (i < n4) {
        float4 v = src[i];
        dst[i] = make_float4(to_tf32(v.x), to_tf32(v.y), to_tf32(v.z), to_tf32(v.w));
    }
}

// c1[e][j] = b1[j] + sum_i W1[j,i]*(t_e*Wt[i]+bt[i])
__global__ void c1_all_kernel(const float* __restrict__ W1, const float* __restrict__ b1,
                              const float* __restrict__ Wt, const float* __restrict__ bt,
                              float dt, float* __restrict__ out) {
    int gw = (blockIdx.x * blockDim.x + threadIdx.x) >> 5;
    int lane = threadIdx.x & 31;
    int e = gw >> 10;
    int j = gw & 1023;
    if (e >= NEVAL) return;
    int step = e >> 2, st = e & 3;
    float tv = step * dt + ((st == 0) ? 0.0f : (st == 3) ? dt : 0.5f * dt);
    const float* row = W1 + (size_t)j * HID;
    float s = 0.0f;
    #pragma unroll 4
    for (int i = lane; i < HID; i += 32)
        s = fmaf(row[i], fmaf(tv, Wt[i], bt[i]), s);
    #pragma unroll
    for (int o = 16; o; o >>= 1) s += __shfl_xor_sync(0xffffffffu, s, o);
    if (lane == 0) out[e * HID2 + j] = b1[j] + s;
}

// ---------------- GEMM: C = act( A[M,K] @ Bw[N,K]^T + bias[N] ) --------------
// R2-proven body + PDL: prefetch weights, griddepcontrol.wait before A,
// launch_dependents after prologue so successor overlaps our tail wave.
// stage < 0 : tanh epilogue, write C (tf32-rounded).
// stage 0..3: fused RK4 epilogue (N == HID).
__global__ __launch_bounds__(256, 2)
void gemm_kernel(const float* __restrict__ A, const float* __restrict__ Bw,
                 const float* __restrict__ bias, float* __restrict__ C,
                 int N, int K, int stage, float dt,
                 float* __restrict__ hbuf, float* __restrict__ accbuf,
                 float* __restrict__ htmp, float* __restrict__ hr) {
    extern __shared__ float smem[];
    const int LDT = 36;                 // padded stride (floats)
    const int STG_F = 128 * LDT;        // floats per stage per matrix
    float* As = smem;                   // 3 stages
    float* Bs = smem + 3 * STG_F;

    const int t = threadIdx.x;
    const int warp = t >> 5, lane = t & 31;
    const int wm = warp & 1, wn = warp >> 1;
    const int g = lane >> 2, q = lane & 3;
    const int bm = blockIdx.y * 128;
    const int bn = blockIdx.x * 128;

    const int c4  = (t & 7) * 4;        // k-offset (floats) this thread copies
    const int r0l = t >> 3;             // first row this thread copies

    const float* Ag = A  + (size_t)(bm + r0l) * K + c4;
    const float* Bg = Bw + (size_t)(bn + r0l) * K + c4;

    const unsigned stgB = STG_F * 4;    // bytes per stage
    unsigned sA0 = (unsigned)__cvta_generic_to_shared(As + r0l * LDT + c4);
    unsigned sB0 = (unsigned)__cvta_generic_to_shared(Bs + r0l * LDT + c4);

    float acc[4][4][4];
    #pragma unroll
    for (int i = 0; i < 4; i++)
        #pragma unroll
        for (int j = 0; j < 4; j++)
            #pragma unroll
            for (int v = 0; v < 4; v++) acc[i][j][v] = 0.0f;

    const int KT = K >> 5;

    #define LOAD_A(kt, s)                                                            \
    {                                                                                \
        const float* ap = Ag + (kt) * 32;                                            \
        unsigned sa = sA0 + (unsigned)(s) * stgB;                                    \
        _Pragma("unroll")                                                            \
        for (int i = 0; i < 4; i++)                                                  \
            asm volatile("cp.async.cg.shared.global [%0], [%1], 16;\n"               \
                         :: "r"(sa + i * 32 * LDT * 4), "l"(ap + (size_t)i * 32 * K)); \
    }
    #define LOAD_B(kt, s)                                                            \
    {                                                                                \
        const float* bp = Bg + (kt) * 32;                                            \
        unsigned sb = sB0 + (unsigned)(s) * stgB;                                    \
        _Pragma("unroll")                                                            \
        for (int i = 0; i < 4; i++)                                                  \
            asm volatile("cp.async.cg.shared.global [%0], [%1], 16;\n"               \
                         :: "r"(sb + i * 32 * LDT * 4), "l"(bp + (size_t)i * 32 * K)); \
    }
    #define COMMIT() asm volatile("cp.async.commit_group;\n")

    // --- prologue: weights first (independent of predecessor), then gate on A ---
    LOAD_B(0, 0);
    LOAD_B(1, 1);
    COMMIT();                                       // group: B0+B1
    asm volatile("griddepcontrol.wait;" ::: "memory");
    LOAD_A(0, 0);
    COMMIT();                                       // group: A0
    LOAD_A(1, 1);
    COMMIT();                                       // group: A1
    asm volatile("griddepcontrol.launch_dependents;" ::: "memory");

    for (int kt = 0; kt < KT; kt++) {
        asm volatile("cp.async.wait_group 1;\n");
        __syncthreads();
        const int cur = kt % 3;
        const float* Asb = As + cur * STG_F;
        const float* Bsb = Bs + cur * STG_F;
        #pragma unroll
        for (int s = 0; s < 4; s++) {
            float af[4][4];
            float bf[4][2];
            #pragma unroll
            for (int fm = 0; fm < 4; fm++) {
                int r0 = wm * 64 + fm * 16 + g;
                af[fm][0] = Asb[r0 * LDT + s * 8 + q];
                af[fm][1] = Asb[(r0 + 8) * LDT + s * 8 + q];
                af[fm][2] = Asb[r0 * LDT + s * 8 + q + 4];
                af[fm][3] = Asb[(r0 + 8) * LDT + s * 8 + q + 4];
            }
            #pragma unroll
            for (int fn = 0; fn < 4; fn++) {
                int c0 = wn * 32 + fn * 8 + g;
                bf[fn][0] = Bsb[c0 * LDT + s * 8 + q];
                bf[fn][1] = Bsb[c0 * LDT + s * 8 + q + 4];
            }
            #pragma unroll
            for (int fm = 0; fm < 4; fm++)
                #pragma unroll
                for (int fn = 0; fn < 4; fn++)
                    mma8(acc[fm][fn], af[fm], bf[fn]);
        }
        if (kt + 2 < KT) {
            const int nxt = (kt + 2) % 3;
            LOAD_A(kt + 2, nxt);
            LOAD_B(kt + 2, nxt);
            COMMIT();
        }
    }
    #undef LOAD_A
    #undef LOAD_B
    #undef COMMIT

    // ---------------- epilogue ----------------
    #pragma unroll
    for (int fm = 0; fm < 4; fm++) {
        int r0 = bm + wm * 64 + fm * 16 + g;
        int r1 = r0 + 8;
        #pragma unroll
        for (int fn = 0; fn < 4; fn++) {
            int c = bn + wn * 32 + fn * 8 + 2 * q;
            float bc0 = bias[c], bc1 = bias[c + 1];
            float v[4];
            v[0] = acc[fm][fn][0] + bc0;
            v[1] = acc[fm][fn][1] + bc1;
            v[2] = acc[fm][fn][2] + bc0;
            v[3] = acc[fm][fn][3] + bc1;
            int idx[4] = { r0 * N + c, r0 * N + c + 1, r1 * N + c, r1 * N + c + 1 };
            if (stage < 0) {
                #pragma unroll
                for (int u = 0; u < 4; u++)
                    C[idx[u]] = to_tf32(tanhf(v[u]));
            } else if (stage == 0) {
                #pragma unroll
                for (int u = 0; u < 4; u++) {
                    accbuf[idx[u]] = v[u];
                    htmp[idx[u]]   = to_tf32(hbuf[idx[u]] + 0.5f * dt * v[u]);
                }
            } else if (stage == 1) {
                #pragma unroll
                for (int u = 0; u < 4; u++) {
                    accbuf[idx[u]] += 2.0f * v[u];
                    htmp[idx[u]]    = to_tf32(hbuf[idx[u]] + 0.5f * dt * v[u]);
                }
            } else if (stage == 2) {
                #pragma unroll
                for (int u = 0; u < 4; u++) {
                    accbuf[idx[u]] += 2.0f * v[u];
                    htmp[idx[u]]    = to_tf32(hbuf[idx[u]] + dt * v[u]);
                }
            } else {
                #pragma unroll
                for (int u = 0; u < 4; u++) {
                    float hn = hbuf[idx[u]] + (dt / 6.0f) * (accbuf[idx[u]] + v[u]);
                    hbuf[idx[u]] = hn;
                    hr[idx[u]]   = to_tf32(hn);
                }
            }
        }
    }
}

// ---------------- launch -----------------------------------------------------
static void launch_gemm(dim3 grd, dim3 blk, int smem,
                        const float* A, const float* Bw, const float* bias, float* C,
                        int N, int K, int stage, float dt,
                        float* hbuf, float* accbuf, float* htmp, float* hr) {
    cudaLaunchConfig_t cfg = {};
    cfg.gridDim = grd;
    cfg.blockDim = blk;
    cfg.dynamicSmemBytes = (size_t)smem;
    cfg.stream = 0;
    cudaLaunchAttribute at[1];
    at[0].id = cudaLaunchAttributeProgrammaticStreamSerialization;
    at[0].val.programmaticStreamSerializationAllowed = 1;
    cfg.attrs = at;
    cfg.numAttrs = 1;
    cudaLaunchKernelEx(&cfg, gemm_kernel, A, Bw, bias, C, N, K, stage, dt,
                       hbuf, accbuf, htmp, hr);
}

extern "C" void kernel_launch(void* const* d_in, const int* in_sizes, int n_in,
                              void* d_out, int out_size) {
    const float* h  = (const float*)d_in[0];
    const float* W1 = (const float*)d_in[1];
    const float* b1 = (const float*)d_in[2];
    const float* W2 = (const float*)d_in[3];
    const float* b2 = (const float*)d_in[4];
    const float* W3 = (const float*)d_in[5];
    const float* b3 = (const float*)d_in[6];
    const float* Wt = (const float*)d_in[7];
    const float* bt = (const float*)d_in[8];
    (void)in_sizes; (void)n_in; (void)out_size;

    float *x1, *x2, *accb, *htmp, *hbuf, *hr, *w1, *w2, *w3, *c1;
    cudaGetSymbolAddress((void**)&x1,   g_x1);
    cudaGetSymbolAddress((void**)&x2,   g_x2);
    cudaGetSymbolAddress((void**)&accb, g_acc);
    cudaGetSymbolAddress((void**)&htmp, g_htmp);
    cudaGetSymbolAddress((void**)&hbuf, g_h);
    cudaGetSymbolAddress((void**)&hr,   g_hr);
    cudaGetSymbolAddress((void**)&w1,   g_w1);
    cudaGetSymbolAddress((void**)&w2,   g_w2);
    cudaGetSymbolAddress((void**)&w3,   g_w3);
    cudaGetSymbolAddress((void**)&c1,   g_c1);

    const int SMEM = 2 * 3 * 128 * 36 * (int)sizeof(float);  // 110592 B
    cudaFuncSetAttribute(gemm_kernel, cudaFuncAttributeMaxDynamicSharedMemorySize, SMEM);

    cudaMemcpyAsync(hbuf, h, (size_t)BATCH * HID * sizeof(float), cudaMemcpyDeviceToDevice);

    const float dt = 1.0f / NSTEPS;

    // prep: tf32-round weights and h, compute all 40 c1 vectors
    {
        int n4;
        n4 = HID2 * HID / 4;   round4_kernel<<<(n4 + 255) / 256, 256>>>((const float4*)W1, (float4*)w1, n4);
        n4 = HID2 * HID2 / 4;  round4_kernel<<<(n4 + 255) / 256, 256>>>((const float4*)W2, (float4*)w2, n4);
        n4 = HID * HID2 / 4;   round4_kernel<<<(n4 + 255) / 256, 256>>>((const float4*)W3, (float4*)w3, n4);
        n4 = BATCH * HID / 4;  round4_kernel<<<(n4 + 255) / 256, 256>>>((const float4*)h,  (float4*)hr, n4);
        c1_all_kernel<<<NEVAL * HID2 / 8, 256>>>(W1, b1, Wt, bt, dt, c1);
    }

    dim3 blk(256);
    dim3 grd1(HID2 / 128, BATCH / 128);    // 8 x 64 = 512 CTAs
    dim3 grd3(HID  / 128, BATCH / 128);    // 4 x 64 = 256 CTAs

    for (int s = 0; s < NSTEPS; s++) {
        for (int st = 0; st < 4; st++) {
            const float* Ain = (st == 0) ? hr : htmp;
            const float* c1e = c1 + (s * 4 + st) * HID2;
            launch_gemm(grd1, blk, SMEM, Ain, w1, c1e, x1, HID2, HID, -1, dt,
                        nullptr, nullptr, nullptr, nullptr);
            launch_gemm(grd1, blk, SMEM, x1, w2, b2, x2, HID2, HID2, -1, dt,
                        nullptr, nullptr, nullptr, nullptr);
            launch_gemm(grd3, blk, SMEM, x2, w3, b3, nullptr, HID, HID2, st, dt,
                        hbuf, accb, htmp, hr);
        }
    }

    cudaMemcpyAsync(d_out, hbuf, (size_t)BATCH * HID * sizeof(float), cudaMemcpyDeviceToDevice);
}